// round 1
// baseline (speedup 1.0000x reference)
#include <cuda_runtime.h>
#include <cstdint>

#define IMG 128
#define BR  512
#define NSTROKES 1024
#define LSTROKES 256

// Scratch (no device mallocs allowed): brush>0 bitmasks + precomputed stroke params.
__device__ uint32_t g_mask[2 * (BR * BR / 32)];   // 16384 words = 64 KB
__device__ float    g_sp[NSTROKES * 16];          // per-stroke: warp 2x3, color rgb, brush idx

// ---------------------------------------------------------------------------
// Kernel 1: per-stroke warp matrix / color / brush-index precompute (1024 thr)
// ---------------------------------------------------------------------------
__global__ void prep_strokes_kernel(const float* __restrict__ params) {
    int n = blockIdx.x * blockDim.x + threadIdx.x;
    if (n >= NSTROKES) return;
    const float* p = params + n * 8;
    float x0 = p[0], y0 = p[1], w = p[2], h = p[3], th = p[4];

    // JAX: sin(fl32(pi) * theta) with f32 product; use correctly-rounded double sin/cos.
    float prod = 3.14159274101257324219f * th;
    float s = (float)sin((double)prod);
    float c = (float)cos((double)prod);

    float tx = 1.0f - 2.0f * x0;
    float ty = 1.0f - 2.0f * y0;
    // H == W == 128 so the H/W, W/H factors are exact power-of-2 scalings that cancel.
    float w00 = c / w;
    float w01 = s / w;
    float w02 = (tx * c) / w + (ty * s) / w;
    float w10 = -(s / h);
    float w11 = c / h;
    float w12 = (ty * c) / h - (tx * s) / h;

    float* o = g_sp + n * 16;
    o[0] = w00; o[1] = w01; o[2] = w02;
    o[3] = w10; o[4] = w11; o[5] = w12;
    o[6] = p[5]; o[7] = p[6]; o[8] = p[7];     // color r,g,b
    o[9] = (h > w) ? 0.0f : 1.0f;              // brush index
    o[10] = o[11] = o[12] = o[13] = o[14] = o[15] = 0.0f;
}

// ---------------------------------------------------------------------------
// Kernel 2: brush>0 bitmask build (one bit per brush texel)
// ---------------------------------------------------------------------------
__global__ void build_mask_kernel(const float* __restrict__ brushes) {
    int i = blockIdx.x * blockDim.x + threadIdx.x;   // 0 .. 2*512*512-1
    float v = brushes[i];
    unsigned bal = __ballot_sync(0xFFFFFFFFu, v > 0.0f);
    if ((threadIdx.x & 31) == 0) g_mask[i >> 5] = bal;
}

// ---------------------------------------------------------------------------
// Kernel 3: render. One thread per (batch, pixel). Backward stroke scan with
// warp-early-exit; last stroke with eroded alpha==1 wins (binary alpha).
// ---------------------------------------------------------------------------
__device__ __forceinline__ bool alpha_at(const uint32_t* __restrict__ m,
                                         float gx, float gy) {
    // nearest sample, matching reference: x = ((gx+1)*512 - 1)*0.5, round-half-even
    float x = ((gx + 1.0f) * 512.0f - 1.0f) * 0.5f;
    float y = ((gy + 1.0f) * 512.0f - 1.0f) * 0.5f;
    int ix = __float2int_rn(x);
    int iy = __float2int_rn(y);
    if ((unsigned)ix >= 512u || (unsigned)iy >= 512u) return false;
    return (m[(iy << 4) + (ix >> 5)] >> (ix & 31)) & 1u;
}

__device__ __forceinline__ float tap(const float* __restrict__ im, int ix, int iy) {
    bool valid = ((unsigned)ix < 512u) && ((unsigned)iy < 512u);
    int cx = min(max(ix, 0), 511);
    int cy = min(max(iy, 0), 511);
    float v = __ldg(im + cy * 512 + cx);
    return valid ? v : 0.0f;
}

__global__ __launch_bounds__(256)
void render_kernel(const float* __restrict__ brushes, float* __restrict__ out) {
    extern __shared__ unsigned char smem[];
    uint32_t* s_mask = (uint32_t*)smem;                    // 16384 words (both brushes)
    float*    s_sp   = (float*)(smem + 65536);             // 256 strokes * 16 floats

    const int b = blockIdx.z;
    const int t = threadIdx.x;

    // Stage bitmasks (64 KB) and this batch's stroke params (16 KB) into shared.
    {
        const uint4* gm = (const uint4*)g_mask;
        uint4* sm4 = (uint4*)s_mask;
        #pragma unroll
        for (int i = 0; i < 16; ++i) sm4[t + i * 256] = gm[t + i * 256];

        const float4* gp = (const float4*)(g_sp + (size_t)b * LSTROKES * 16);
        float4* sp4 = (float4*)s_sp;
        #pragma unroll
        for (int i = 0; i < 4; ++i) sp4[t * 4 + i] = gp[t * 4 + i];
    }
    __syncthreads();

    const int tx = t & 15, ty = t >> 4;
    const int w = blockIdx.x * 16 + tx;
    const int h = blockIdx.y * 16 + ty;
    const float bx = (2.0f * (float)w + 1.0f) * (1.0f / 128.0f) - 1.0f;  // exact
    const float by = (2.0f * (float)h + 1.0f) * (1.0f / 128.0f) - 1.0f;  // exact

    float oR = 0.0f, oG = 0.0f, oB = 0.0f;
    bool done = false;

    for (int l = LSTROKES - 1; l >= 0; --l) {
        if (__all_sync(0xFFFFFFFFu, done)) break;
        if (!done) {
            const float* sp = s_sp + l * 16;
            const float w00 = sp[0], w01 = sp[1], w02 = sp[2];
            const float w10 = sp[3], w11 = sp[4], w12 = sp[5];
            const int   idx = (sp[9] != 0.0f) ? 1 : 0;
            const uint32_t* m = s_mask + (idx << 13);

            float gx = fmaf(bx, w00, fmaf(by, w01, w02));
            float gy = fmaf(bx, w10, fmaf(by, w11, w12));

            // Center alpha first (cheap reject).
            if (alpha_at(m, gx, gy)) {
                // 3x3 erosion: min over in-image neighbors (pad value ignored).
                bool ok = true;
                #pragma unroll
                for (int k = 0; k < 9; ++k) {
                    const int dh = k / 3 - 1, dw = k % 3 - 1;
                    if (dh == 0 && dw == 0) continue;
                    if ((unsigned)(h + dh) >= 128u) continue;
                    if ((unsigned)(w + dw) >= 128u) continue;
                    // exact base-grid shifts (1/64 is a power of two)
                    const float bxn = bx + (float)dw * 0.015625f;
                    const float byn = by + (float)dh * 0.015625f;
                    const float gxn = fmaf(bxn, w00, fmaf(byn, w01, w02));
                    const float gyn = fmaf(bxn, w10, fmaf(byn, w11, w12));
                    ok &= alpha_at(m, gxn, gyn);
                }
                if (ok) {
                    // Winner: one bilinear sample of the brush.
                    const float* im = brushes + (size_t)idx * (BR * BR);
                    const float x = ((gx + 1.0f) * 512.0f - 1.0f) * 0.5f;
                    const float y = ((gy + 1.0f) * 512.0f - 1.0f) * 0.5f;
                    const float xf = floorf(x), yf = floorf(y);
                    const int x0i = (int)xf, y0i = (int)yf;
                    const float wx1 = x - xf, wx0 = 1.0f - wx1;
                    const float wy1 = y - yf, wy0 = 1.0f - wy1;
                    const float sV =
                        tap(im, x0i,     y0i)     * (wx0 * wy0) +
                        tap(im, x0i + 1, y0i)     * (wx1 * wy0) +
                        tap(im, x0i,     y0i + 1) * (wx0 * wy1) +
                        tap(im, x0i + 1, y0i + 1) * (wx1 * wy1);
                    oR = sV * sp[6];
                    oG = sV * sp[7];
                    oB = sV * sp[8];
                    done = true;
                }
            }
        }
    }

    const int base = ((b * 3) * IMG + h) * IMG + w;
    out[base]                 = oR;
    out[base + IMG * IMG]     = oG;
    out[base + 2 * IMG * IMG] = oB;
}

// ---------------------------------------------------------------------------
extern "C" void kernel_launch(void* const* d_in, const int* in_sizes, int n_in,
                              void* d_out, int out_size) {
    const float* params  = (const float*)d_in[0];   // (4,256,8)
    const float* brushes = (const float*)d_in[1];   // (2,1,512,512)
    float* out = (float*)d_out;                     // (4,3,128,128)

    (void)in_sizes; (void)n_in; (void)out_size;

    prep_strokes_kernel<<<4, 256>>>(params);
    build_mask_kernel<<<(2 * BR * BR) / 256, 256>>>(brushes);

    const int smem_bytes = 16384 * 4 + LSTROKES * 16 * 4;  // 81920
    cudaFuncSetAttribute(render_kernel,
                         cudaFuncAttributeMaxDynamicSharedMemorySize, smem_bytes);
    dim3 grid(IMG / 16, IMG / 16, 4);
    render_kernel<<<grid, 256, smem_bytes>>>(brushes, out);
}

// round 2
// speedup vs baseline: 1.1828x; 1.1828x over previous
#include <cuda_runtime.h>
#include <cstdint>

#define IMG 128
#define BR  512
#define NSTROKES 1024
#define LSTROKES 256

// Scratch (no device mallocs allowed): brush>0 bitmasks + precomputed stroke params.
__device__ uint32_t g_mask[2 * (BR * BR / 32)];   // 16384 words = 64 KB
__device__ float    g_sp[NSTROKES * 16];          // per-stroke: warp 2x3, color rgb, brush idx

// ---------------------------------------------------------------------------
// Kernel 1 (fused): blocks [0,64) build the brush>0 bitmask (one 32-bit word
// per thread, consuming exactly one 128B cache line); blocks [64,96) compute
// per-stroke warp matrices (1 warp per block -> fp64 sin/cos spread over 32
// SMs instead of 4).
// ---------------------------------------------------------------------------
__global__ void prep_and_mask_kernel(const float* __restrict__ params,
                                     const float* __restrict__ brushes) {
    const int bid = blockIdx.x;
    const int t = threadIdx.x;

    if (bid < 64) {
        // word index 0 .. 16383 ; each word = 32 consecutive brush texels
        const int word = bid * 256 + t;
        const float4* src = (const float4*)brushes + word * 8;
        uint32_t m = 0;
        #pragma unroll
        for (int j = 0; j < 8; ++j) {
            float4 v = src[j];
            m |= ((v.x > 0.0f) ? 1u : 0u) << (4 * j + 0);
            m |= ((v.y > 0.0f) ? 1u : 0u) << (4 * j + 1);
            m |= ((v.z > 0.0f) ? 1u : 0u) << (4 * j + 2);
            m |= ((v.w > 0.0f) ? 1u : 0u) << (4 * j + 3);
        }
        g_mask[word] = m;
    } else {
        if (t >= 32) return;
        const int n = (bid - 64) * 32 + t;          // 0 .. 1023
        const float* p = params + n * 8;
        float x0 = p[0], y0 = p[1], w = p[2], h = p[3], th = p[4];

        // JAX: sin(fl32(pi) * theta) with f32 product; correctly-rounded double
        // sin/cos of the f32 product keeps binary-alpha decisions bit-stable.
        float prod = 3.14159274101257324219f * th;
        float s = (float)sin((double)prod);
        float c = (float)cos((double)prod);

        float tx = 1.0f - 2.0f * x0;
        float ty = 1.0f - 2.0f * y0;
        // H == W == 128: the H/W, W/H factors cancel exactly.
        float w00 = c / w;
        float w01 = s / w;
        float w02 = (tx * c) / w + (ty * s) / w;
        float w10 = -(s / h);
        float w11 = c / h;
        float w12 = (ty * c) / h - (tx * s) / h;

        float* o = g_sp + n * 16;
        o[0] = w00; o[1] = w01; o[2] = w02;
        o[3] = w10; o[4] = w11; o[5] = w12;
        o[6] = p[5]; o[7] = p[6]; o[8] = p[7];     // color r,g,b
        o[9] = (h > w) ? 0.0f : 1.0f;              // brush index
        o[10] = o[11] = o[12] = o[13] = o[14] = o[15] = 0.0f;
    }
}

// ---------------------------------------------------------------------------
// Kernel 2: render. One thread per (batch, pixel). Backward stroke scan with
// warp-early-exit; last stroke with eroded alpha==1 wins (binary alpha).
// ---------------------------------------------------------------------------
__device__ __forceinline__ bool alpha_at(const uint32_t* __restrict__ m,
                                         float gx, float gy) {
    // nearest sample, matching reference: x = ((gx+1)*512 - 1)*0.5, round-half-even
    float x = ((gx + 1.0f) * 512.0f - 1.0f) * 0.5f;
    float y = ((gy + 1.0f) * 512.0f - 1.0f) * 0.5f;
    int ix = __float2int_rn(x);
    int iy = __float2int_rn(y);
    if ((unsigned)ix >= 512u || (unsigned)iy >= 512u) return false;
    return (m[(iy << 4) + (ix >> 5)] >> (ix & 31)) & 1u;
}

__device__ __forceinline__ float tap(const float* __restrict__ im, int ix, int iy) {
    bool valid = ((unsigned)ix < 512u) && ((unsigned)iy < 512u);
    int cx = min(max(ix, 0), 511);
    int cy = min(max(iy, 0), 511);
    float v = __ldg(im + cy * 512 + cx);
    return valid ? v : 0.0f;
}

__global__ __launch_bounds__(256)
void render_kernel(const float* __restrict__ brushes, float* __restrict__ out) {
    extern __shared__ unsigned char smem[];
    uint32_t* s_mask = (uint32_t*)smem;                    // 16384 words (both brushes)
    float*    s_sp   = (float*)(smem + 65536);             // 256 strokes * 16 floats

    const int b = blockIdx.z;
    const int t = threadIdx.x;

    // Stage bitmasks (64 KB) and this batch's stroke params (16 KB) into shared.
    {
        const uint4* gm = (const uint4*)g_mask;
        uint4* sm4 = (uint4*)s_mask;
        #pragma unroll
        for (int i = 0; i < 16; ++i) sm4[t + i * 256] = gm[t + i * 256];

        const float4* gp = (const float4*)(g_sp + (size_t)b * LSTROKES * 16);
        float4* sp4 = (float4*)s_sp;
        #pragma unroll
        for (int i = 0; i < 4; ++i) sp4[t * 4 + i] = gp[t * 4 + i];
    }
    __syncthreads();

    const int tx = t & 15, ty = t >> 4;
    const int w = blockIdx.x * 16 + tx;
    const int h = blockIdx.y * 16 + ty;
    const float bx = (2.0f * (float)w + 1.0f) * (1.0f / 128.0f) - 1.0f;  // exact
    const float by = (2.0f * (float)h + 1.0f) * (1.0f / 128.0f) - 1.0f;  // exact

    float oR = 0.0f, oG = 0.0f, oB = 0.0f;
    bool done = false;

    for (int l = LSTROKES - 1; l >= 0; --l) {
        if (__all_sync(0xFFFFFFFFu, done)) break;
        if (!done) {
            const float* sp = s_sp + l * 16;
            const float w00 = sp[0], w01 = sp[1], w02 = sp[2];
            const float w10 = sp[3], w11 = sp[4], w12 = sp[5];
            const int   idx = (sp[9] != 0.0f) ? 1 : 0;
            const uint32_t* m = s_mask + (idx << 13);

            float gx = fmaf(bx, w00, fmaf(by, w01, w02));
            float gy = fmaf(bx, w10, fmaf(by, w11, w12));

            // Center alpha first (cheap reject).
            if (alpha_at(m, gx, gy)) {
                // 3x3 erosion: min over in-image neighbors (pad value ignored).
                bool ok = true;
                #pragma unroll
                for (int k = 0; k < 9; ++k) {
                    const int dh = k / 3 - 1, dw = k % 3 - 1;
                    if (dh == 0 && dw == 0) continue;
                    if ((unsigned)(h + dh) >= 128u) continue;
                    if ((unsigned)(w + dw) >= 128u) continue;
                    // exact base-grid shifts (1/64 is a power of two)
                    const float bxn = bx + (float)dw * 0.015625f;
                    const float byn = by + (float)dh * 0.015625f;
                    const float gxn = fmaf(bxn, w00, fmaf(byn, w01, w02));
                    const float gyn = fmaf(bxn, w10, fmaf(byn, w11, w12));
                    ok &= alpha_at(m, gxn, gyn);
                }
                if (ok) {
                    // Winner: one bilinear sample of the brush.
                    const float* im = brushes + (size_t)idx * (BR * BR);
                    const float x = ((gx + 1.0f) * 512.0f - 1.0f) * 0.5f;
                    const float y = ((gy + 1.0f) * 512.0f - 1.0f) * 0.5f;
                    const float xf = floorf(x), yf = floorf(y);
                    const int x0i = (int)xf, y0i = (int)yf;
                    const float wx1 = x - xf, wx0 = 1.0f - wx1;
                    const float wy1 = y - yf, wy0 = 1.0f - wy1;
                    const float sV =
                        tap(im, x0i,     y0i)     * (wx0 * wy0) +
                        tap(im, x0i + 1, y0i)     * (wx1 * wy0) +
                        tap(im, x0i,     y0i + 1) * (wx0 * wy1) +
                        tap(im, x0i + 1, y0i + 1) * (wx1 * wy1);
                    oR = sV * sp[6];
                    oG = sV * sp[7];
                    oB = sV * sp[8];
                    done = true;
                }
            }
        }
    }

    const int base = ((b * 3) * IMG + h) * IMG + w;
    out[base]                 = oR;
    out[base + IMG * IMG]     = oG;
    out[base + 2 * IMG * IMG] = oB;
}

// ---------------------------------------------------------------------------
extern "C" void kernel_launch(void* const* d_in, const int* in_sizes, int n_in,
                              void* d_out, int out_size) {
    const float* params  = (const float*)d_in[0];   // (4,256,8)
    const float* brushes = (const float*)d_in[1];   // (2,1,512,512)
    float* out = (float*)d_out;                     // (4,3,128,128)

    (void)in_sizes; (void)n_in; (void)out_size;

    // 64 mask blocks + 32 prep blocks (fp64 sin/cos spread over 32 SMs)
    prep_and_mask_kernel<<<96, 256>>>(params, brushes);

    const int smem_bytes = 16384 * 4 + LSTROKES * 16 * 4;  // 81920
    cudaFuncSetAttribute(render_kernel,
                         cudaFuncAttributeMaxDynamicSharedMemorySize, smem_bytes);
    dim3 grid(IMG / 16, IMG / 16, 4);
    render_kernel<<<grid, 256, smem_bytes>>>(brushes, out);
}